// round 13
// baseline (speedup 1.0000x reference)
#include <cuda_runtime.h>
#include <cuda_bf16.h>
#include <math.h>
#include <stdint.h>

#define BATCH    512
#define NCLS     100000
#define DIM      512
#define CM       64                 /* classes per tile */
#define TILES    1563               /* ceil(NCLS/64) */
#define CPAD     (TILES * CM)       /* 100032 */
#define HB       256                /* batch rows per CTA (half) */
#define STRIPS   74                 /* CTAs per half -> 148 total */
#define S_SCALE  30.0f
#define SHIFT    30.0f
#define N_U      110.0f
#define N_L      10.0f
#define M_U      1.0f
#define M_L      0.1f
#define LAMBDA_G 35.0f
#define PI_F     3.14159265358979323846f
#define WSC      64.0f              /* W pre-scale before e4m3 */
#define LOG2E    1.44269504f
#define ARG_SCALE 43.2808512f       /* 30*log2(e) */
#define ARG_BIAS  (-43.2808512f)

#define PITCH    528                /* x-hat smem row pitch bytes (512+16) */
#define TILE_B   32768              /* bytes per fp8 W tile in fragment layout */

/* dynamic smem layout (bytes) */
#define OFF_SX    0                         /* 256 x 528 = 135168 */
#define OFF_LAB   135168                    /* int[256]   = 1024 */
#define OFF_AT    136192                    /* float[256] = 1024 */
#define SMEM_BYTES 137216

// ---------------- static device scratch ----------------
__device__ uint8_t  g_wq[(size_t)CPAD * DIM]; // W e4m3, per-lane fragment layout (51 MB)
__device__ float    g_invn[CPAD];             // invn * ARG_SCALE (pad rows 0)
__device__ uint8_t  g_xq[BATCH * DIM];        // x-hat e4m3
__device__ float    g_xnf[BATCH * DIM];       // x-hat fp32 (exact target dot)
__device__ float4   g_mp[BATCH];
__device__ float    g_xnorm_cl[BATCH];
__device__ float    g_tlogit[BATCH];
__device__ float    g_argt[BATCH];
__device__ int      g_labels[BATCH];
__device__ float    g_sumB[BATCH];
__device__ unsigned g_maxB32[BATCH];

__device__ __forceinline__ unsigned fenc(float f) {
    unsigned u = __float_as_uint(f);
    return (u & 0x80000000u) ? ~u : (u | 0x80000000u);
}
__device__ __forceinline__ float ex2(float x) {
    float r;
    asm("ex2.approx.ftz.f32 %0, %1;" : "=f"(r) : "f"(x));
    return r;
}
__device__ __forceinline__ unsigned short cvt_e4m3x2(float hi, float lo) {
    unsigned short r;
    asm("cvt.rn.satfinite.e4m3x2.f32 %0, %1, %2;" : "=h"(r) : "f"(hi), "f"(lo));
    return r;
}
__device__ __forceinline__ void cpa16(uint32_t dst, const void* src) {
    asm volatile("cp.async.cg.shared.global [%0], [%1], 16;" :: "r"(dst), "l"(src));
}
__device__ __forceinline__ void ldsm_x4(uint32_t addr, unsigned& r0, unsigned& r1,
                                        unsigned& r2, unsigned& r3) {
    asm volatile("ldmatrix.sync.aligned.m8n8.x4.shared.b16 {%0,%1,%2,%3}, [%4];"
                 : "=r"(r0), "=r"(r1), "=r"(r2), "=r"(r3) : "r"(addr));
}

// ---------------- labels (+ per-call accumulator zeroing) ----------------
__global__ void k_labels(const void* lab) {
    __shared__ int s_is64;
    int tid = threadIdx.x;
    if (tid == 0) s_is64 = 1;
    __syncthreads();
    if (tid < BATCH / 2) {
        long long v = ((const long long*)lab)[tid];
        if (v < 0 || v >= (long long)NCLS) s_is64 = 0;
    }
    __syncthreads();
    if (tid < BATCH) {
        int v;
        if (s_is64) v = (int)((const long long*)lab)[tid];
        else        v = ((const int*)lab)[tid];
        g_labels[tid] = v;
        g_sumB[tid] = 0.0f;
        g_maxB32[tid] = 0u;
    }
}

// ---------------- x: norms, margin params, fp32 + fp8 normalize ----------------
__global__ void k_prep_x(const float* __restrict__ x) {
    int row = blockIdx.x;
    int t = threadIdx.x;  // 128
    float4 v = ((const float4*)(x + (size_t)row * DIM))[t];
    float ss = v.x * v.x + v.y * v.y + v.z * v.z + v.w * v.w;
    #pragma unroll
    for (int o = 16; o; o >>= 1) ss += __shfl_xor_sync(0xffffffffu, ss, o);
    __shared__ float s[4];
    if ((t & 31) == 0) s[t >> 5] = ss;
    __syncthreads();
    float tot = s[0] + s[1] + s[2] + s[3];
    float nrm = sqrtf(tot);
    float inv = 1.0f / nrm;
    if (t == 0) {
        float a = fminf(fmaxf(nrm, N_L), N_U);
        float m = (M_U - M_L) / (N_U - N_L) * (a - N_L) + M_L;
        g_mp[row] = make_float4(cosf(m), sinf(m), cosf(PI_F - m), sinf(PI_F - m) * m);
        g_xnorm_cl[row] = a;
    }
    float f0 = v.x * inv, f1 = v.y * inv, f2 = v.z * inv, f3 = v.w * inv;
    ((float4*)(g_xnf + (size_t)row * DIM))[t] = make_float4(f0, f1, f2, f3);
    unsigned short lo = cvt_e4m3x2(f1, f0);
    unsigned short hi = cvt_e4m3x2(f3, f2);
    ((uint32_t*)(g_xq + (size_t)row * DIM))[t] = (uint32_t)lo | ((uint32_t)hi << 16);
}

// ---------------- exact fp32 target-class logit ----------------
__global__ void k_target(const float* __restrict__ W) {
    int b = blockIdx.x;
    int t = threadIdx.x;  // 128
    int lab = g_labels[b];
    float4 wv = ((const float4*)(W + (size_t)lab * DIM))[t];
    float4 xv = ((const float4*)(g_xnf + (size_t)b * DIM))[t];
    float dot = wv.x * xv.x + wv.y * xv.y + wv.z * xv.z + wv.w * xv.w;
    float ssq = wv.x * wv.x + wv.y * wv.y + wv.z * wv.z + wv.w * wv.w;
    #pragma unroll
    for (int o = 16; o; o >>= 1) {
        dot += __shfl_xor_sync(0xffffffffu, dot, o);
        ssq += __shfl_xor_sync(0xffffffffu, ssq, o);
    }
    __shared__ float sd[4], sq[4];
    if ((t & 31) == 0) { sd[t >> 5] = dot; sq[t >> 5] = ssq; }
    __syncthreads();
    if (t == 0) {
        float d = sd[0] + sd[1] + sd[2] + sd[3];
        float q = sq[0] + sq[1] + sq[2] + sq[3];
        float cs = d * rsqrtf(q);
        float4 mp = g_mp[b];
        float sine = sqrtf(fmaxf(0.0f, 1.0f - cs * cs));
        float phi = cs * mp.x - sine * mp.y;
        float tl = ((cs - mp.z > 0.0f) ? phi : (cs - mp.w)) * S_SCALE;
        g_tlogit[b] = tl;
        g_argt[b] = (tl - SHIFT) * LOG2E;
    }
}

// ---------------- W fp32 -> fp8 in per-lane mma fragment layout ----------------
// Layout: tile t (64 rows x 512 k-bytes) -> 32KB at g_wq + t*32768:
//   group (ks, wm, mt) = 512B at offset (ks*4 + wm*2 + mt)*512; lane L owns 16B:
//   [row g k(tg*4), row g+8 k(tg*4), row g k(16+tg*4), row g+8 k(16+tg*4)]
//   where g=L>>2, tg=L&3, rows relative to (t*64 + wm*32 + mt*16), k rel. ks*32.
__global__ void k_convw(const float* __restrict__ W) {
    __shared__ uint32_t st[TILE_B / 4];      // 32 KB staging
    int t = blockIdx.x;
    int u = threadIdx.x;                     // 256
    int rr = u >> 2, seg = u & 3;            // 4 threads per row
    int R = t * CM + rr;
    bool val = R < NCLS;
    const float4* src = (const float4*)(W + (size_t)(val ? R : 0) * DIM) + seg * 32;
    int wm = rr >> 5, mt = (rr >> 4) & 1, hi8 = (rr >> 3) & 1, g = rr & 7;
    float ssq = 0.0f;
    #pragma unroll
    for (int j = 0; j < 32; j++) {
        uint32_t word = 0u;
        if (val) {
            float4 v = src[j];
            float a = v.x * WSC, b = v.y * WSC, c = v.z * WSC, d = v.w * WSC;
            ssq += a * a + b * b + c * c + d * d;
            unsigned short lo = cvt_e4m3x2(b, a);
            unsigned short hi = cvt_e4m3x2(d, c);
            word = (uint32_t)lo | ((uint32_t)hi << 16);
        }
        int f0 = seg * 128 + 4 * j;
        int ks = f0 >> 5, o = f0 & 31;
        int khalf = o >> 4, tg = (o >> 2) & 3;
        int off = (ks * 4 + wm * 2 + mt) * 512 + (g * 4 + tg) * 16 + (khalf * 2 + hi8) * 4;
        st[off >> 2] = word;
    }
    ssq += __shfl_xor_sync(0xffffffffu, ssq, 1);
    ssq += __shfl_xor_sync(0xffffffffu, ssq, 2);
    if (seg == 0)
        g_invn[t * CM + rr] = (val && ssq > 0.f) ? rsqrtf(ssq) * ARG_SCALE : 0.f;
    __syncthreads();
    uint4* dst = (uint4*)(g_wq + (size_t)t * TILE_B);
    const uint4* s4 = (const uint4*)st;
    #pragma unroll
    for (int j = 0; j < 8; j++) dst[u * 8 + j] = s4[u * 8 + j];
}

// ---------------- barrier-free persistent-strip FP8 GEMM ----------------
// A-fragments LDG'd directly from g_wq (fragment layout, 2-deep pipeline);
// B (x-hat) resident in smem; no W smem, no per-tile barrier — warps free-run.
__global__ void __launch_bounds__(512, 1) k_gemm() {
    extern __shared__ char smem[];
    uint32_t sbase = (uint32_t)__cvta_generic_to_shared(smem);
    uint32_t sx_u = sbase + OFF_SX;
    int* s_lab = (int*)(smem + OFF_LAB);
    float* s_at = (float*)(smem + OFF_AT);

    int tid = threadIdx.x;
    int strip = blockIdx.x, half = blockIdx.y;
    int hbase = half * HB;

    if (tid < HB) {
        s_lab[tid] = g_labels[hbase + tid];
        s_at[tid]  = g_argt[hbase + tid];
    }

    // resident x-hat load
    #pragma unroll
    for (int j = 0; j < 16; j++) {
        int idx = tid + j * 512;
        int r = idx >> 5, ch = idx & 31;
        cpa16(sx_u + (uint32_t)(r * PITCH + ch * 16),
              g_xq + (size_t)(hbase + r) * DIM + ch * 16);
    }
    asm volatile("cp.async.commit_group;");
    asm volatile("cp.async.wait_group 0;" ::: "memory");
    __syncthreads();      // the only block-wide barrier

    int warp = tid >> 5, lane = tid & 31;
    int wm = warp & 1;        // M half (0..1) of 64 classes
    int wn = warp >> 1;       // N eighth (0..7) of 256 batch
    int g = lane >> 2, tg = lane & 3;

    int b_lrow = wn * 32 + (lane & 7) + (lane >> 4) * 8;
    int b_lkb  = ((lane >> 3) & 1) * 16;
    uint32_t b_addr0 = sx_u + (uint32_t)(b_lrow * PITCH + b_lkb);
    uint32_t b_addr1 = sx_u + (uint32_t)((b_lrow + 16) * PITCH + b_lkb);

    // per-column register state across all tiles
    float lsum[8], amax[8]; int labtile[8];
    #pragma unroll
    for (int nt = 0; nt < 4; nt++)
        #pragma unroll
        for (int lo = 0; lo < 2; lo++) {
            int j = nt * 2 + lo;
            int lcol = wn * 32 + nt * 8 + 2 * tg + lo;
            labtile[j] = s_lab[lcol] >> 6;
            lsum[j] = 0.0f;
            amax[j] = -1e30f;
        }

    const uint8_t* wbase = g_wq + (size_t)wm * 1024 + (size_t)lane * 16;
    const uint8_t* pt = wbase + (size_t)strip * TILE_B;
    int ntiles = (TILES - strip + STRIPS - 1) / STRIPS;

    // 2-deep A prefetch pipeline
    uint4 pre[2][2];
    pre[0][0] = *(const uint4*)(pt);
    pre[0][1] = *(const uint4*)(pt + 512);
    pre[1][0] = *(const uint4*)(pt + 2048);
    pre[1][1] = *(const uint4*)(pt + 2048 + 512);

    #pragma unroll 1
    for (int ti = 0; ti < ntiles; ti++) {
        int t = strip + ti * STRIPS;
        const uint8_t* ptn = (ti + 1 < ntiles) ? pt + (size_t)STRIPS * TILE_B : pt;

        float inv43[2][2];
        #pragma unroll
        for (int mt = 0; mt < 2; mt++)
            #pragma unroll
            for (int hi = 0; hi < 2; hi++)
                inv43[mt][hi] = g_invn[t * CM + wm * 32 + mt * 16 + g + hi * 8];

        float acc[2][4][4];
        #pragma unroll
        for (int mt = 0; mt < 2; mt++)
            #pragma unroll
            for (int nt = 0; nt < 4; nt++)
                #pragma unroll
                for (int e = 0; e < 4; e++) acc[mt][nt][e] = 0.0f;

        #pragma unroll
        for (int ks = 0; ks < 16; ks++) {
            int par = ks & 1;
            uint4 a0 = pre[par][0], a1 = pre[par][1];
            // prefetch k-step ks+2 (rolls into next tile at ks=14,15)
            const uint8_t* pp = (ks < 14) ? (pt + (ks + 2) * 2048)
                                          : (ptn + (ks - 14) * 2048);
            pre[par][0] = *(const uint4*)(pp);
            pre[par][1] = *(const uint4*)(pp + 512);

            int kb = ks * 32;
            #pragma unroll
            for (int p = 0; p < 2; p++) {
                unsigned b0, b1, b2, b3;
                ldsm_x4((p ? b_addr1 : b_addr0) + (uint32_t)kb, b0, b1, b2, b3);
                asm volatile(
                    "mma.sync.aligned.m16n8k32.row.col.f32.e4m3.e4m3.f32 "
                    "{%0,%1,%2,%3},{%4,%5,%6,%7},{%8,%9},{%0,%1,%2,%3};\n"
                    : "+f"(acc[0][2 * p][0]), "+f"(acc[0][2 * p][1]),
                      "+f"(acc[0][2 * p][2]), "+f"(acc[0][2 * p][3])
                    : "r"(a0.x), "r"(a0.y), "r"(a0.z), "r"(a0.w), "r"(b0), "r"(b1));
                asm volatile(
                    "mma.sync.aligned.m16n8k32.row.col.f32.e4m3.e4m3.f32 "
                    "{%0,%1,%2,%3},{%4,%5,%6,%7},{%8,%9},{%0,%1,%2,%3};\n"
                    : "+f"(acc[0][2 * p + 1][0]), "+f"(acc[0][2 * p + 1][1]),
                      "+f"(acc[0][2 * p + 1][2]), "+f"(acc[0][2 * p + 1][3])
                    : "r"(a0.x), "r"(a0.y), "r"(a0.z), "r"(a0.w), "r"(b2), "r"(b3));
                asm volatile(
                    "mma.sync.aligned.m16n8k32.row.col.f32.e4m3.e4m3.f32 "
                    "{%0,%1,%2,%3},{%4,%5,%6,%7},{%8,%9},{%0,%1,%2,%3};\n"
                    : "+f"(acc[1][2 * p][0]), "+f"(acc[1][2 * p][1]),
                      "+f"(acc[1][2 * p][2]), "+f"(acc[1][2 * p][3])
                    : "r"(a1.x), "r"(a1.y), "r"(a1.z), "r"(a1.w), "r"(b0), "r"(b1));
                asm volatile(
                    "mma.sync.aligned.m16n8k32.row.col.f32.e4m3.e4m3.f32 "
                    "{%0,%1,%2,%3},{%4,%5,%6,%7},{%8,%9},{%0,%1,%2,%3};\n"
                    : "+f"(acc[1][2 * p + 1][0]), "+f"(acc[1][2 * p + 1][1]),
                      "+f"(acc[1][2 * p + 1][2]), "+f"(acc[1][2 * p + 1][3])
                    : "r"(a1.x), "r"(a1.y), "r"(a1.z), "r"(a1.w), "r"(b2), "r"(b3));
            }
        }

        // slim epilogue (no barrier): arg = acc*inv43 + bias; exp2-sum + max
        #pragma unroll
        for (int nt = 0; nt < 4; nt++) {
            #pragma unroll
            for (int lo = 0; lo < 2; lo++) {
                const int j = nt * 2 + lo;
                float a[4];
                #pragma unroll
                for (int mt = 0; mt < 2; mt++)
                    #pragma unroll
                    for (int hi = 0; hi < 2; hi++)
                        a[mt * 2 + hi] =
                            fmaf(acc[mt][nt][hi * 2 + lo], inv43[mt][hi], ARG_BIAS);
                if (labtile[j] == t) {            // rare: label in this tile
                    int lcol = wn * 32 + nt * 8 + 2 * tg + lo;
                    int lab = s_lab[lcol];
                    float at = s_at[lcol];
                    #pragma unroll
                    for (int mt = 0; mt < 2; mt++)
                        #pragma unroll
                        for (int hi = 0; hi < 2; hi++) {
                            int ccls = t * CM + wm * 32 + mt * 16 + g + hi * 8;
                            if (ccls == lab) a[mt * 2 + hi] = at;
                        }
                }
                #pragma unroll
                for (int e = 0; e < 4; e++) {
                    lsum[j] += ex2(a[e]);
                    amax[j] = fmaxf(amax[j], a[e]);
                }
            }
        }
        pt = ptn;
    }

    // single end-of-kernel reduction + atomics
    #pragma unroll
    for (int nt = 0; nt < 4; nt++) {
        #pragma unroll
        for (int lo = 0; lo < 2; lo++) {
            const int j = nt * 2 + lo;
            float s = lsum[j], m = amax[j];
            #pragma unroll
            for (int off = 4; off < 32; off <<= 1) {
                s += __shfl_xor_sync(0xffffffffu, s, off);
                m = fmaxf(m, __shfl_xor_sync(0xffffffffu, m, off));
            }
            if (g == 0) {
                int lcol = wn * 32 + nt * 8 + 2 * tg + lo;
                atomicAdd(&g_sumB[hbase + lcol], s);
                atomicMax(&g_maxB32[hbase + lcol], fenc(m));
            }
        }
    }
}

// ---------------- final scalar outputs ----------------
__global__ void k_final(float* __restrict__ out, int out_size) {
    int b = threadIdx.x;  // 512
    float sum = g_sumB[b] - 32.0f * ex2(ARG_BIAS);   // remove zero-pad rows exactly
    float lse = logf(sum) + SHIFT;
    float ce = lse - g_tlogit[b];
    float corr = (g_maxB32[b] == fenc(g_argt[b])) ? 1.0f : 0.0f;
    float a = g_xnorm_cl[b];
    float gt = a / (N_U * N_U) + 1.0f / a;

    __shared__ float s1[512], s2[512], s3[512];
    s1[b] = ce; s2[b] = corr; s3[b] = gt;
    __syncthreads();
    for (int o = 256; o; o >>= 1) {
        if (b < o) { s1[b] += s1[b + o]; s2[b] += s2[b + o]; s3[b] += s3[b + o]; }
        __syncthreads();
    }
    if (b == 0) {
        float loss = s1[0] / (float)BATCH + LAMBDA_G * (s3[0] / (float)BATCH);
        if (out_size >= 1) out[0] = loss;
        if (out_size >= 2) out[1] = s2[0] / (float)BATCH * 100.0f;
    }
    if (b >= 2 && b < out_size) out[b] = 0.0f;
}

extern "C" void kernel_launch(void* const* d_in, const int* in_sizes, int n_in,
                              void* d_out, int out_size) {
    const float* x = (const float*)d_in[0];
    const void* lab = d_in[1];
    const float* w = (const float*)d_in[2];
    (void)in_sizes; (void)n_in;

    cudaFuncSetAttribute(k_gemm, cudaFuncAttributeMaxDynamicSharedMemorySize, SMEM_BYTES);

    k_labels<<<1, 512>>>(lab);
    k_prep_x<<<BATCH, 128>>>(x);
    k_target<<<BATCH, 128>>>(w);
    k_convw<<<TILES, 256>>>(w);
    dim3 grid(STRIPS, 2);
    k_gemm<<<grid, 512, SMEM_BYTES>>>();
    k_final<<<1, 512>>>((float*)d_out, out_size);
}

// round 17
// speedup vs baseline: 1.3995x; 1.3995x over previous
#include <cuda_runtime.h>
#include <cuda_bf16.h>
#include <math.h>
#include <stdint.h>

#define BATCH    512
#define NCLS     100000
#define DIM      512
#define CM       64                 /* classes per tile */
#define TILES    1563               /* ceil(NCLS/64) */
#define CPAD     (TILES * CM)       /* 100032 */
#define HB       256                /* batch rows per CTA (half) */
#define STRIPS   74                 /* CTAs per half -> 148 total */
#define S_SCALE  30.0f
#define SHIFT    30.0f
#define N_U      110.0f
#define N_L      10.0f
#define M_U      1.0f
#define M_L      0.1f
#define LAMBDA_G 35.0f
#define PI_F     3.14159265358979323846f
#define WSC      64.0f              /* W pre-scale before e4m3 */
#define LOG2E    1.44269504f
#define ARG_SCALE 43.2808512f       /* 30*log2(e) */
#define ARG_BIAS  (-43.2808512f)

#define PITCH    528                /* x-hat smem row pitch bytes (512+16) */
#define TILE_B   32768              /* bytes per fp8 W tile in fragment layout */

/* dynamic smem layout (bytes) */
#define OFF_SX    0                         /* 256 x 528 = 135168 */
#define OFF_LAB   135168                    /* int[256]   = 1024 */
#define OFF_AT    136192                    /* float[256] = 1024 */
#define SMEM_BYTES 137216

// ---------------- static device scratch ----------------
__device__ uint8_t  g_wq[(size_t)CPAD * DIM]; // W e4m3, per-lane fragment layout (51 MB)
__device__ float    g_invn[CPAD];             // invn * ARG_SCALE (pad rows 0)
__device__ uint8_t  g_xq[BATCH * DIM];        // x-hat e4m3
__device__ float    g_xnf[BATCH * DIM];       // x-hat fp32 (exact target dot)
__device__ float4   g_mp[BATCH];
__device__ float    g_xnorm_cl[BATCH];
__device__ float    g_tlogit[BATCH];
__device__ float    g_argt[BATCH];
__device__ int      g_labels[BATCH];
__device__ float    g_sumB[BATCH];
__device__ unsigned g_maxB32[BATCH];

__device__ __forceinline__ unsigned fenc(float f) {
    unsigned u = __float_as_uint(f);
    return (u & 0x80000000u) ? ~u : (u | 0x80000000u);
}
__device__ __forceinline__ float ex2(float x) {
    float r;
    asm("ex2.approx.ftz.f32 %0, %1;" : "=f"(r) : "f"(x));
    return r;
}
__device__ __forceinline__ unsigned short cvt_e4m3x2(float hi, float lo) {
    unsigned short r;
    asm("cvt.rn.satfinite.e4m3x2.f32 %0, %1, %2;" : "=h"(r) : "f"(hi), "f"(lo));
    return r;
}
__device__ __forceinline__ void cpa16(uint32_t dst, const void* src) {
    asm volatile("cp.async.cg.shared.global [%0], [%1], 16;" :: "r"(dst), "l"(src));
}
__device__ __forceinline__ void ldsm_x4(uint32_t addr, unsigned& r0, unsigned& r1,
                                        unsigned& r2, unsigned& r3) {
    asm volatile("ldmatrix.sync.aligned.m8n8.x4.shared.b16 {%0,%1,%2,%3}, [%4];"
                 : "=r"(r0), "=r"(r1), "=r"(r2), "=r"(r3) : "r"(addr));
}

// ---------------- labels (+ per-call accumulator zeroing) ----------------
__global__ void k_labels(const void* lab) {
    __shared__ int s_is64;
    int tid = threadIdx.x;
    if (tid == 0) s_is64 = 1;
    __syncthreads();
    if (tid < BATCH / 2) {
        long long v = ((const long long*)lab)[tid];
        if (v < 0 || v >= (long long)NCLS) s_is64 = 0;
    }
    __syncthreads();
    if (tid < BATCH) {
        int v;
        if (s_is64) v = (int)((const long long*)lab)[tid];
        else        v = ((const int*)lab)[tid];
        g_labels[tid] = v;
        g_sumB[tid] = 0.0f;
        g_maxB32[tid] = 0u;
    }
}

// ---------------- x: norms, margin params, fp32 + fp8 normalize ----------------
__global__ void k_prep_x(const float* __restrict__ x) {
    int row = blockIdx.x;
    int t = threadIdx.x;  // 128
    float4 v = ((const float4*)(x + (size_t)row * DIM))[t];
    float ss = v.x * v.x + v.y * v.y + v.z * v.z + v.w * v.w;
    #pragma unroll
    for (int o = 16; o; o >>= 1) ss += __shfl_xor_sync(0xffffffffu, ss, o);
    __shared__ float s[4];
    if ((t & 31) == 0) s[t >> 5] = ss;
    __syncthreads();
    float tot = s[0] + s[1] + s[2] + s[3];
    float nrm = sqrtf(tot);
    float inv = 1.0f / nrm;
    if (t == 0) {
        float a = fminf(fmaxf(nrm, N_L), N_U);
        float m = (M_U - M_L) / (N_U - N_L) * (a - N_L) + M_L;
        g_mp[row] = make_float4(cosf(m), sinf(m), cosf(PI_F - m), sinf(PI_F - m) * m);
        g_xnorm_cl[row] = a;
    }
    float f0 = v.x * inv, f1 = v.y * inv, f2 = v.z * inv, f3 = v.w * inv;
    ((float4*)(g_xnf + (size_t)row * DIM))[t] = make_float4(f0, f1, f2, f3);
    unsigned short lo = cvt_e4m3x2(f1, f0);
    unsigned short hi = cvt_e4m3x2(f3, f2);
    ((uint32_t*)(g_xq + (size_t)row * DIM))[t] = (uint32_t)lo | ((uint32_t)hi << 16);
}

// ---------------- exact fp32 target-class logit ----------------
__global__ void k_target(const float* __restrict__ W) {
    int b = blockIdx.x;
    int t = threadIdx.x;  // 128
    int lab = g_labels[b];
    float4 wv = ((const float4*)(W + (size_t)lab * DIM))[t];
    float4 xv = ((const float4*)(g_xnf + (size_t)b * DIM))[t];
    float dot = wv.x * xv.x + wv.y * xv.y + wv.z * xv.z + wv.w * xv.w;
    float ssq = wv.x * wv.x + wv.y * wv.y + wv.z * wv.z + wv.w * wv.w;
    #pragma unroll
    for (int o = 16; o; o >>= 1) {
        dot += __shfl_xor_sync(0xffffffffu, dot, o);
        ssq += __shfl_xor_sync(0xffffffffu, ssq, o);
    }
    __shared__ float sd[4], sq[4];
    if ((t & 31) == 0) { sd[t >> 5] = dot; sq[t >> 5] = ssq; }
    __syncthreads();
    if (t == 0) {
        float d = sd[0] + sd[1] + sd[2] + sd[3];
        float q = sq[0] + sq[1] + sq[2] + sq[3];
        float cs = d * rsqrtf(q);
        float4 mp = g_mp[b];
        float sine = sqrtf(fmaxf(0.0f, 1.0f - cs * cs));
        float phi = cs * mp.x - sine * mp.y;
        float tl = ((cs - mp.z > 0.0f) ? phi : (cs - mp.w)) * S_SCALE;
        g_tlogit[b] = tl;
        g_argt[b] = (tl - SHIFT) * LOG2E;
    }
}

// ---------------- W fp32 -> fp8 fragment layout (MLP-fixed, 1024 thr/tile) ----------------
// Layout: tile t -> 32KB; group (ks, grp)*512B; lane 16B fragment.
// grp = row>>4 within tile; g = row&7; hi8 = (row>>3)&1; float4 j: ks=j>>3,
// khalf=(j>>2)&1, tg=j&3. Each of 16 threads/row handles 8 float4 (j = seg+it*16).
__global__ void __launch_bounds__(1024) k_convw(const float* __restrict__ W) {
    __shared__ uint32_t st[TILE_B / 4];      // 32 KB staging
    int t = blockIdx.x;
    int u = threadIdx.x;                     // 1024
    int rr = u >> 4, seg = u & 15;           // row 0..63, seg 0..15
    int R = t * CM + rr;
    bool val = R < NCLS;
    const float4* src = (const float4*)(W + (size_t)(val ? R : 0) * DIM);
    int grp = rr >> 4, rm = rr & 15, hi8 = rm >> 3, g = rm & 7;
    float ssq = 0.0f;
    #pragma unroll
    for (int it = 0; it < 8; it++) {
        int j = seg + it * 16;               // float4 index 0..127
        uint32_t word = 0u;
        if (val) {
            float4 v = src[j];
            float a = v.x * WSC, b = v.y * WSC, c = v.z * WSC, d = v.w * WSC;
            ssq += a * a + b * b + c * c + d * d;
            unsigned short lo = cvt_e4m3x2(b, a);
            unsigned short hi = cvt_e4m3x2(d, c);
            word = (uint32_t)lo | ((uint32_t)hi << 16);
        }
        int ks = j >> 3, khalf = (j >> 2) & 1, tg = j & 3;
        int off = (ks * 4 + grp) * 512 + (g * 4 + tg) * 16 + (khalf * 2 + hi8) * 4;
        st[off >> 2] = word;
    }
    ssq += __shfl_xor_sync(0xffffffffu, ssq, 1);
    ssq += __shfl_xor_sync(0xffffffffu, ssq, 2);
    ssq += __shfl_xor_sync(0xffffffffu, ssq, 4);
    ssq += __shfl_xor_sync(0xffffffffu, ssq, 8);
    if (seg == 0)
        g_invn[t * CM + rr] = (val && ssq > 0.f) ? rsqrtf(ssq) * ARG_SCALE : 0.f;
    __syncthreads();
    uint4* dst = (uint4*)(g_wq + (size_t)t * TILE_B);
    const uint4* s4 = (const uint4*)st;
    dst[u * 2] = s4[u * 2];
    dst[u * 2 + 1] = s4[u * 2 + 1];
}

// ---------------- barrier-free persistent-strip FP8 GEMM, 32 warps ----------------
// 1024 threads = 32 warps as 4(M:16) x 8(N:32). A via direct LDG.128 from
// fragment-layout g_wq (2-deep pipeline); B resident in smem; warps free-run.
__global__ void __launch_bounds__(1024, 1) k_gemm() {
    extern __shared__ char smem[];
    uint32_t sbase = (uint32_t)__cvta_generic_to_shared(smem);
    uint32_t sx_u = sbase + OFF_SX;
    int* s_lab = (int*)(smem + OFF_LAB);
    float* s_at = (float*)(smem + OFF_AT);

    int tid = threadIdx.x;
    int strip = blockIdx.x, half = blockIdx.y;
    int hbase = half * HB;

    if (tid < HB) {
        s_lab[tid] = g_labels[hbase + tid];
        s_at[tid]  = g_argt[hbase + tid];
    }

    // resident x-hat load
    #pragma unroll
    for (int j = 0; j < 8; j++) {
        int idx = tid + j * 1024;
        int r = idx >> 5, ch = idx & 31;
        cpa16(sx_u + (uint32_t)(r * PITCH + ch * 16),
              g_xq + (size_t)(hbase + r) * DIM + ch * 16);
    }
    asm volatile("cp.async.commit_group;");
    asm volatile("cp.async.wait_group 0;" ::: "memory");
    __syncthreads();      // the only block-wide barrier

    int warp = tid >> 5, lane = tid & 31;
    int wm = warp & 3;        // m16 tile (0..3) within 64 classes
    int wn = warp >> 2;       // N eighth (0..7) of 256 batch
    int g = lane >> 2, tg = lane & 3;

    int b_lrow = wn * 32 + (lane & 7) + (lane >> 4) * 8;
    int b_lkb  = ((lane >> 3) & 1) * 16;
    uint32_t b_addr0 = sx_u + (uint32_t)(b_lrow * PITCH + b_lkb);
    uint32_t b_addr1 = sx_u + (uint32_t)((b_lrow + 16) * PITCH + b_lkb);

    // per-column register state across all tiles (8 cols/thread)
    float lsum[8], amax[8];
    #pragma unroll
    for (int j = 0; j < 8; j++) { lsum[j] = 0.0f; amax[j] = -1e30f; }

    const uint8_t* wbase = g_wq + (size_t)wm * 512 + (size_t)lane * 16;
    const uint8_t* pt = wbase + (size_t)strip * TILE_B;
    int ntiles = (TILES - strip + STRIPS - 1) / STRIPS;

    // 2-deep A prefetch pipeline (1 uint4 per k-step)
    uint4 pre[2];
    pre[0] = *(const uint4*)(pt);
    pre[1] = *(const uint4*)(pt + 2048);

    #pragma unroll 1
    for (int ti = 0; ti < ntiles; ti++) {
        int t = strip + ti * STRIPS;
        const uint8_t* ptn = (ti + 1 < ntiles) ? pt + (size_t)STRIPS * TILE_B : pt;

        float inv43[2];
        #pragma unroll
        for (int hi = 0; hi < 2; hi++)
            inv43[hi] = g_invn[t * CM + wm * 16 + g + hi * 8];

        float acc[4][4];
        #pragma unroll
        for (int nt = 0; nt < 4; nt++)
            #pragma unroll
            for (int e = 0; e < 4; e++) acc[nt][e] = 0.0f;

        #pragma unroll
        for (int ks = 0; ks < 16; ks++) {
            int par = ks & 1;
            uint4 a0 = pre[par];
            // prefetch k-step ks+2 (rolls into next tile at ks=14,15)
            const uint8_t* pp = (ks < 14) ? (pt + (ks + 2) * 2048)
                                          : (ptn + (ks - 14) * 2048);
            pre[par] = *(const uint4*)(pp);

            int kb = ks * 32;
            unsigned b0, b1, b2, b3, b4, b5, b6, b7;
            ldsm_x4(b_addr0 + (uint32_t)kb, b0, b1, b2, b3);
            ldsm_x4(b_addr1 + (uint32_t)kb, b4, b5, b6, b7);
            asm volatile(
                "mma.sync.aligned.m16n8k32.row.col.f32.e4m3.e4m3.f32 "
                "{%0,%1,%2,%3},{%4,%5,%6,%7},{%8,%9},{%0,%1,%2,%3};\n"
                : "+f"(acc[0][0]), "+f"(acc[0][1]), "+f"(acc[0][2]), "+f"(acc[0][3])
                : "r"(a0.x), "r"(a0.y), "r"(a0.z), "r"(a0.w), "r"(b0), "r"(b1));
            asm volatile(
                "mma.sync.aligned.m16n8k32.row.col.f32.e4m3.e4m3.f32 "
                "{%0,%1,%2,%3},{%4,%5,%6,%7},{%8,%9},{%0,%1,%2,%3};\n"
                : "+f"(acc[1][0]), "+f"(acc[1][1]), "+f"(acc[1][2]), "+f"(acc[1][3])
                : "r"(a0.x), "r"(a0.y), "r"(a0.z), "r"(a0.w), "r"(b2), "r"(b3));
            asm volatile(
                "mma.sync.aligned.m16n8k32.row.col.f32.e4m3.e4m3.f32 "
                "{%0,%1,%2,%3},{%4,%5,%6,%7},{%8,%9},{%0,%1,%2,%3};\n"
                : "+f"(acc[2][0]), "+f"(acc[2][1]), "+f"(acc[2][2]), "+f"(acc[2][3])
                : "r"(a0.x), "r"(a0.y), "r"(a0.z), "r"(a0.w), "r"(b4), "r"(b5));
            asm volatile(
                "mma.sync.aligned.m16n8k32.row.col.f32.e4m3.e4m3.f32 "
                "{%0,%1,%2,%3},{%4,%5,%6,%7},{%8,%9},{%0,%1,%2,%3};\n"
                : "+f"(acc[3][0]), "+f"(acc[3][1]), "+f"(acc[3][2]), "+f"(acc[3][3])
                : "r"(a0.x), "r"(a0.y), "r"(a0.z), "r"(a0.w), "r"(b6), "r"(b7));
        }

        // slim epilogue (no barrier): arg = acc*inv43 + bias; exp2-sum + max
        #pragma unroll
        for (int nt = 0; nt < 4; nt++) {
            #pragma unroll
            for (int lo = 0; lo < 2; lo++) {
                const int j = nt * 2 + lo;
                int lcol = wn * 32 + nt * 8 + 2 * tg + lo;
                float a0v = fmaf(acc[nt][lo],     inv43[0], ARG_BIAS);
                float a1v = fmaf(acc[nt][lo + 2], inv43[1], ARG_BIAS);
                int lab = s_lab[lcol];
                if ((lab >> 6) == t) {            // rare: label in this tile
                    float at = s_at[lcol];
                    int c0 = t * CM + wm * 16 + g;
                    if (c0 == lab) a0v = at;
                    if (c0 + 8 == lab) a1v = at;
                }
                lsum[j] += ex2(a0v) + ex2(a1v);
                amax[j] = fmaxf(amax[j], fmaxf(a0v, a1v));
            }
        }
        pt = ptn;
    }

    // single end-of-kernel reduction + atomics
    #pragma unroll
    for (int nt = 0; nt < 4; nt++) {
        #pragma unroll
        for (int lo = 0; lo < 2; lo++) {
            const int j = nt * 2 + lo;
            float s = lsum[j], m = amax[j];
            #pragma unroll
            for (int off = 4; off < 32; off <<= 1) {
                s += __shfl_xor_sync(0xffffffffu, s, off);
                m = fmaxf(m, __shfl_xor_sync(0xffffffffu, m, off));
            }
            if (g == 0) {
                int lcol = wn * 32 + nt * 8 + 2 * tg + lo;
                // 4 M-warps (wm) hit the same column: atomics merge them
                atomicAdd(&g_sumB[hbase + lcol], s);
                atomicMax(&g_maxB32[hbase + lcol], fenc(m));
            }
        }
    }
}

// ---------------- final scalar outputs ----------------
__global__ void k_final(float* __restrict__ out, int out_size) {
    int b = threadIdx.x;  // 512
    float sum = g_sumB[b] - 32.0f * ex2(ARG_BIAS);   // remove zero-pad rows exactly
    float lse = logf(sum) + SHIFT;
    float ce = lse - g_tlogit[b];
    float corr = (g_maxB32[b] == fenc(g_argt[b])) ? 1.0f : 0.0f;
    float a = g_xnorm_cl[b];
    float gt = a / (N_U * N_U) + 1.0f / a;

    __shared__ float s1[512], s2[512], s3[512];
    s1[b] = ce; s2[b] = corr; s3[b] = gt;
    __syncthreads();
    for (int o = 256; o; o >>= 1) {
        if (b < o) { s1[b] += s1[b + o]; s2[b] += s2[b + o]; s3[b] += s3[b + o]; }
        __syncthreads();
    }
    if (b == 0) {
        float loss = s1[0] / (float)BATCH + LAMBDA_G * (s3[0] / (float)BATCH);
        if (out_size >= 1) out[0] = loss;
        if (out_size >= 2) out[1] = s2[0] / (float)BATCH * 100.0f;
    }
    if (b >= 2 && b < out_size) out[b] = 0.0f;
}

extern "C" void kernel_launch(void* const* d_in, const int* in_sizes, int n_in,
                              void* d_out, int out_size) {
    const float* x = (const float*)d_in[0];
    const void* lab = d_in[1];
    const float* w = (const float*)d_in[2];
    (void)in_sizes; (void)n_in;

    cudaFuncSetAttribute(k_gemm, cudaFuncAttributeMaxDynamicSharedMemorySize, SMEM_BYTES);

    k_labels<<<1, 512>>>(lab);
    k_prep_x<<<BATCH, 128>>>(x);
    k_target<<<BATCH, 128>>>(w);
    k_convw<<<TILES, 1024>>>(w);
    dim3 grid(STRIPS, 2);
    k_gemm<<<grid, 1024, SMEM_BYTES>>>();
    k_final<<<1, 512>>>((float*)d_out, out_size);
}